// round 8
// baseline (speedup 1.0000x reference)
#include <cuda_runtime.h>
#include <math.h>

#define D_MODEL   3072
#define NUM_E     8
#define N_TOKENS  16384
#define TPW       4                       // tokens per warp-quad
#define WARPS_PB  16
#define THREADS   (WARPS_PB * 32)         // 512
#define NCHUNK    24                      // 24 stages of 128 d
#define PF        4                       // LDG pipeline depth (register ring)
#define GRID      148
#define NWARPS_G  (GRID * WARPS_PB)       // 2368
#define NQUADS    (N_TOKENS / TPW)        // 4096
#define ROW_F4    (D_MODEL / 4)           // 768 float4 per token row
#define SMEM_BYTES (NUM_E * D_MODEL * 4)  // 96 KB: transposed, paired W

typedef unsigned long long u64;

__device__ __forceinline__ u64 ffma2(u64 a, u64 b, u64 c) {
    u64 d;
    asm("fma.rn.f32x2 %0, %1, %2, %3;" : "=l"(d) : "l"(a), "l"(b), "l"(c));
    return d;
}
__device__ __forceinline__ u64 addf2(u64 a, u64 b) {
    u64 d;
    asm("add.rn.f32x2 %0, %1, %2;" : "=l"(d) : "l"(a), "l"(b));
    return d;
}
__device__ __forceinline__ u64 dup2(float f) {
    u64 r; unsigned u = __float_as_uint(f);
    asm("mov.b64 %0, {%1, %1};" : "=l"(r) : "r"(u));
    return r;
}
__device__ __forceinline__ u64 shflx64(u64 v, int m) {
    unsigned lo = (unsigned)v, hi = (unsigned)(v >> 32);
    lo = __shfl_xor_sync(0xFFFFFFFFu, lo, m);
    hi = __shfl_xor_sync(0xFFFFFFFFu, hi, m);
    return ((u64)hi << 32) | lo;
}
// sWt layout: row d = 8 floats (e0..e7) = 32 B; halves h=0 (e0..3) / h=1 (e4..7).
// Swizzle 16B granule with (d>>2)&7 so lanes (consecutive d*4) hit distinct banks.
__device__ __forceinline__ unsigned wt_off(int d, int h) {
    unsigned o = (unsigned)d * 32u + (unsigned)h * 16u;
    return o ^ ((((unsigned)d >> 2) & 7u) << 4);
}

__global__ void __launch_bounds__(THREADS, 1)
gating_kernel(const float* __restrict__ x,
              const float* __restrict__ W,
              const float* __restrict__ b,
              float* __restrict__ out,
              int idx_off)
{
    extern __shared__ char sWt[];   // 96 KB transposed+paired W

    // Build sWt: sWt[d][e] = W[e][d], bank-swizzled. Global reads coalesced
    // (consecutive lanes -> consecutive d for fixed e).
    for (int d = threadIdx.x; d < D_MODEL; d += THREADS) {
        #pragma unroll
        for (int e = 0; e < NUM_E; ++e) {
            float v = W[e * D_MODEL + d];
            *reinterpret_cast<float*>(sWt + wt_off(d, e >> 2) + (e & 3) * 4) = v;
        }
    }
    __syncthreads();

    const int warp = threadIdx.x >> 5;
    const int lane = threadIdx.x & 31;
    const int bid  = blockIdx.x;

    // Persistent: quads q0 and (maybe) q0 + 2368 (R4-best schedule).
    const int q0 = bid + GRID * warp;                 // < 2368
    const int nq = (q0 + NWARPS_G < NQUADS) ? 2 : 1;
    const int T  = nq * NCHUNK;

    // stage t -> quad j = t/24, chunk c = t%24; lane owns d = c*128 + lane*4 .. +3
    float4 xpf[PF][TPW];

    #define ISSUE(t_)                                                          \
        do {                                                                   \
            int _t = (t_);                                                     \
            int _j = _t / NCHUNK;                                              \
            int _c = _t - _j * NCHUNK;                                         \
            const float4* _s = reinterpret_cast<const float4*>(                \
                x + (size_t)(q0 + _j * NWARPS_G) * (TPW * D_MODEL)             \
                  + _c * 128) + lane;                                          \
            _Pragma("unroll")                                                  \
            for (int _tt = 0; _tt < TPW; ++_tt)                                \
                xpf[(_t) & (PF - 1)][_tt] = __ldcs(_s + _tt * ROW_F4);         \
        } while (0)

    u64 acc[TPW][4];   // (e0,e1),(e2,e3),(e4,e5),(e6,e7) per token
    #pragma unroll
    for (int t = 0; t < TPW; ++t)
        #pragma unroll
        for (int p = 0; p < 4; ++p)
            acc[t][p] = 0ull;

    // Prologue: 4 stages in flight.
    ISSUE(0); ISSUE(1); ISSUE(2); ISSUE(3);

    #pragma unroll 4
    for (int t = 0; t < T; ++t) {
        const int j = t / NCHUNK;
        const int c = t - j * NCHUNK;
        const int dbase = c * 128 + lane * 4;
        const int slot = t & (PF - 1);

        // One K-step: d = dbase + k, x component = xv.{x,y,z,w}
        #define KSTEP(k_, comp_)                                               \
            do {                                                               \
                const ulonglong2 w01 = *reinterpret_cast<const ulonglong2*>(   \
                    sWt + wt_off(dbase + (k_), 0));                            \
                const ulonglong2 w45 = *reinterpret_cast<const ulonglong2*>(   \
                    sWt + wt_off(dbase + (k_), 1));                            \
                _Pragma("unroll")                                              \
                for (int _tt = 0; _tt < TPW; ++_tt) {                          \
                    const u64 a = dup2(xpf[slot][_tt].comp_);                  \
                    acc[_tt][0] = ffma2(a, w01.x, acc[_tt][0]);                \
                    acc[_tt][1] = ffma2(a, w01.y, acc[_tt][1]);                \
                    acc[_tt][2] = ffma2(a, w45.x, acc[_tt][2]);                \
                    acc[_tt][3] = ffma2(a, w45.y, acc[_tt][3]);                \
                }                                                              \
            } while (0)

        KSTEP(0, x);
        KSTEP(1, y);
        KSTEP(2, z);
        KSTEP(3, w);
        #undef KSTEP

        // Refill the slot just consumed (WAR handled by in-order issue).
        if (t + PF < T) ISSUE(t + PF);

        if (c == NCHUNK - 1) {
            // ---- epilogue for quad q0 + j*NWARPS_G ----
            const int tok0 = (q0 + j * NWARPS_G) * TPW;

            // Butterfly reduce packed accumulators across the warp.
            #pragma unroll
            for (int off = 16; off > 0; off >>= 1)
                #pragma unroll
                for (int tt = 0; tt < TPW; ++tt)
                    #pragma unroll
                    for (int p = 0; p < 4; ++p)
                        acc[tt][p] = addf2(acc[tt][p], shflx64(acc[tt][p], off));

            if (lane < TPW) {
                const int tok = tok0 + lane;

                float logit[NUM_E];
                #pragma unroll
                for (int p = 0; p < 4; ++p) {
                    logit[2 * p]     = __uint_as_float((unsigned)acc[lane][p])
                                       + __ldg(&b[2 * p]);
                    logit[2 * p + 1] = __uint_as_float((unsigned)(acc[lane][p] >> 32))
                                       + __ldg(&b[2 * p + 1]);
                }

                float m = logit[0];
                #pragma unroll
                for (int e = 1; e < NUM_E; ++e) m = fmaxf(m, logit[e]);

                float ex[NUM_E], Z = 0.0f;
                #pragma unroll
                for (int e = 0; e < NUM_E; ++e) { ex[e] = __expf(logit[e] - m); Z += ex[e]; }
                const float invZ = 1.0f / Z;

                float sc[NUM_E];
                #pragma unroll
                for (int e = 0; e < NUM_E; ++e) sc[e] = ex[e] * invZ;

                int i1 = 0;
                #pragma unroll
                for (int e = 1; e < NUM_E; ++e) if (sc[e] > sc[i1]) i1 = e;
                int i2 = (i1 == 0) ? 1 : 0;
                #pragma unroll
                for (int e = 0; e < NUM_E; ++e)
                    if (e != i1 && sc[e] > sc[i2]) i2 = e;

                const float v1 = sc[i1];
                const float v2 = sc[i2];
                const float e2 = __expf(v2 - v1);
                const float r1 = 1.0f / (1.0f + e2);
                const float r2 = 1.0f - r1;

                out[(size_t)tok * 2 + 0] = r1;
                out[(size_t)tok * 2 + 1] = r2;
                out[(size_t)idx_off + (size_t)tok * 2 + 0] = (float)i1;
                out[(size_t)idx_off + (size_t)tok * 2 + 1] = (float)i2;
            }

            // Reset accumulators for the next quad.
            #pragma unroll
            for (int tt = 0; tt < TPW; ++tt)
                #pragma unroll
                for (int p = 0; p < 4; ++p)
                    acc[tt][p] = 0ull;
        }
    }
    #undef ISSUE
}

extern "C" void kernel_launch(void* const* d_in, const int* in_sizes, int n_in,
                              void* d_out, int out_size)
{
    const float* x = (const float*)d_in[0];
    const float* W = (const float*)d_in[1];
    const float* b = (const float*)d_in[2];
    float* out = (float*)d_out;

    const int idx_off = out_size / 2;

    cudaFuncSetAttribute(gating_kernel,
                         cudaFuncAttributeMaxDynamicSharedMemorySize,
                         (int)SMEM_BYTES);

    gating_kernel<<<GRID, THREADS, SMEM_BYTES>>>(x, W, b, out, idx_off);
}

// round 9
// speedup vs baseline: 1.3844x; 1.3844x over previous
#include <cuda_runtime.h>
#include <math.h>

#define D_MODEL   3072
#define NUM_E     8
#define N_TOKENS  16384
#define TPW       4                       // tokens per warp-quad
#define WARPS_PB  16
#define THREADS   (WARPS_PB * 32)         // 512
#define CHUNK_D   128                     // floats of D per pipeline stage
#define NCHUNK    (D_MODEL / CHUNK_D)     // 24 (divisible by NSTAGE=4)
#define NSTAGE    4                       // per-warp ring depth (3 in flight)
#define GRID      148
#define NWARPS_G  (GRID * WARPS_PB)       // 2368
#define NQUADS    (N_TOKENS / TPW)        // 4096
#define ROW_V     (D_MODEL / 4)           // 768 16B elems per W row
#define STAGE_BYTES (TPW * CHUNK_D * 4)   // 2048
#define RING_FLOATS_PER_WARP (NSTAGE * TPW * CHUNK_D)    // 2048 floats = 8 KB
#define SMEM_BYTES ((NUM_E * D_MODEL + WARPS_PB * RING_FLOATS_PER_WARP) * 4)  // 224 KB

typedef unsigned long long u64;

__device__ __forceinline__ u64 ffma2(u64 a, u64 b, u64 c) {
    u64 d;
    asm("fma.rn.f32x2 %0, %1, %2, %3;" : "=l"(d) : "l"(a), "l"(b), "l"(c));
    return d;
}
__device__ __forceinline__ float unpack_sum(u64 v) {
    return __uint_as_float((unsigned)(v & 0xFFFFFFFFull)) +
           __uint_as_float((unsigned)(v >> 32));
}

__global__ void __launch_bounds__(THREADS, 1)
gating_kernel(const float* __restrict__ x,
              const float* __restrict__ W,
              const float* __restrict__ b,
              float* __restrict__ out,
              int idx_off)
{
    extern __shared__ float smem[];
    float* sW = smem;                                   // [8][3072]
    float* sX = smem + NUM_E * D_MODEL;                 // per-warp rings

    {
        const float4* Wv = reinterpret_cast<const float4*>(W);
        float4* sWv4 = reinterpret_cast<float4*>(sW);
        #pragma unroll 4
        for (int i = threadIdx.x; i < NUM_E * D_MODEL / 4; i += THREADS)
            sWv4[i] = Wv[i];
    }
    __syncthreads();

    const int warp = threadIdx.x >> 5;
    const int lane = threadIdx.x & 31;
    const int bid  = blockIdx.x;

    float* ring = sX + warp * RING_FLOATS_PER_WARP;
    const unsigned ring_s =
        (unsigned)__cvta_generic_to_shared(ring) + lane * 16;
    const ulonglong2* __restrict__ ringv =
        reinterpret_cast<const ulonglong2*>(ring);
    const ulonglong2* __restrict__ sWv =
        reinterpret_cast<const ulonglong2*>(sW);

    // Persistent schedule (R4-proven): quads q0 and maybe q0 + 2368.
    const int q0 = bid + GRID * warp;                 // < 2368
    const int nq = (q0 + NWARPS_G < NQUADS) ? 2 : 1;

    const size_t QSTRIDE = (size_t)NWARPS_G * (TPW * D_MODEL);
    const float* cur = x + (size_t)q0 * (TPW * D_MODEL) + lane * 4;

    // Issue stage (chunk c_ of quad at base_) into ring slot slot_.
    // All offsets are compile-time constants at expansion sites.
    #define ISSUE(base_, c_, slot_)                                           \
        do {                                                                  \
            const float* _s = (base_) + (c_) * CHUNK_D;                       \
            unsigned _d = ring_s + (slot_) * STAGE_BYTES;                     \
            _Pragma("unroll")                                                 \
            for (int _tt = 0; _tt < TPW; ++_tt)                               \
                asm volatile("cp.async.cg.shared.global [%0], [%1], 16;"      \
                             :: "r"(_d + _tt * (CHUNK_D * 4)),                \
                                "l"(_s + (size_t)_tt * D_MODEL));             \
        } while (0)
    #define COMMIT() asm volatile("cp.async.commit_group;" ::: "memory")
    #define WAITG2() asm volatile("cp.async.wait_group 2;" ::: "memory")

    u64 acc[TPW][NUM_E];
    #pragma unroll
    for (int t = 0; t < TPW; ++t)
        #pragma unroll
        for (int e = 0; e < NUM_E; ++e)
            acc[t][e] = 0ull;

    // Prologue: 3 stages in flight.
    ISSUE(cur, 0, 0); COMMIT();
    ISSUE(cur, 1, 1); COMMIT();
    ISSUE(cur, 2, 2); COMMIT();

    for (int j = 0; j < nq; ++j) {
        const float* nxt = cur + QSTRIDE;
        const bool more = (j + 1 < nq);

        #pragma unroll
        for (int c = 0; c < NCHUNK; ++c) {
            WAITG2();   // stage (j,c) complete; 2 newer still pending

            // Keep 3 in flight: issue stage c+3 (this quad or the next).
            if (c < NCHUNK - 3) {
                ISSUE(cur, c + 3, (c + 3) & 3);
            } else if (more) {
                ISSUE(nxt, c + 3 - NCHUNK, (c + 3) & 3);
            }
            COMMIT();

            // Compute stage (c, slot c&3): all smem offsets static.
            const ulonglong2* xs = ringv + (c & 3) * (TPW * CHUNK_D / 4);
            ulonglong2 xv[TPW];
            #pragma unroll
            for (int tt = 0; tt < TPW; ++tt)
                xv[tt] = xs[tt * (CHUNK_D / 4) + lane];

            #pragma unroll
            for (int e = 0; e < NUM_E; ++e) {
                const ulonglong2 wv =
                    sWv[e * ROW_V + c * (CHUNK_D / 4) + lane];
                #pragma unroll
                for (int tt = 0; tt < TPW; ++tt) {
                    acc[tt][e] = ffma2(xv[tt].x, wv.x, acc[tt][e]);
                    acc[tt][e] = ffma2(xv[tt].y, wv.y, acc[tt][e]);
                }
            }
        }

        // ---- epilogue for quad q0 + j*NWARPS_G ----
        {
            const int tok0 = (q0 + j * NWARPS_G) * TPW;

            float red[TPW][NUM_E];
            #pragma unroll
            for (int tt = 0; tt < TPW; ++tt)
                #pragma unroll
                for (int e = 0; e < NUM_E; ++e) {
                    red[tt][e] = unpack_sum(acc[tt][e]);
                    acc[tt][e] = 0ull;
                }

            #pragma unroll
            for (int off = 16; off > 0; off >>= 1)
                #pragma unroll
                for (int tt = 0; tt < TPW; ++tt)
                    #pragma unroll
                    for (int e = 0; e < NUM_E; ++e)
                        red[tt][e] += __shfl_xor_sync(0xFFFFFFFFu, red[tt][e], off);

            if (lane < TPW) {
                const int tok = tok0 + lane;

                float logit[NUM_E];
                #pragma unroll
                for (int e = 0; e < NUM_E; ++e)
                    logit[e] = red[lane][e] + __ldg(&b[e]);

                float m = logit[0];
                #pragma unroll
                for (int e = 1; e < NUM_E; ++e) m = fmaxf(m, logit[e]);

                float ex[NUM_E], Z = 0.0f;
                #pragma unroll
                for (int e = 0; e < NUM_E; ++e) { ex[e] = __expf(logit[e] - m); Z += ex[e]; }
                const float invZ = 1.0f / Z;

                float sc[NUM_E];
                #pragma unroll
                for (int e = 0; e < NUM_E; ++e) sc[e] = ex[e] * invZ;

                int i1 = 0;
                #pragma unroll
                for (int e = 1; e < NUM_E; ++e) if (sc[e] > sc[i1]) i1 = e;
                int i2 = (i1 == 0) ? 1 : 0;
                #pragma unroll
                for (int e = 0; e < NUM_E; ++e)
                    if (e != i1 && sc[e] > sc[i2]) i2 = e;

                const float v1 = sc[i1];
                const float v2 = sc[i2];
                const float e2 = __expf(v2 - v1);
                const float r1 = 1.0f / (1.0f + e2);
                const float r2 = 1.0f - r1;

                out[(size_t)tok * 2 + 0] = r1;
                out[(size_t)tok * 2 + 1] = r2;
                out[(size_t)idx_off + (size_t)tok * 2 + 0] = (float)i1;
                out[(size_t)idx_off + (size_t)tok * 2 + 1] = (float)i2;
            }
        }

        cur = nxt;
    }
    #undef ISSUE
    #undef COMMIT
    #undef WAITG2
}

extern "C" void kernel_launch(void* const* d_in, const int* in_sizes, int n_in,
                              void* d_out, int out_size)
{
    const float* x = (const float*)d_in[0];
    const float* W = (const float*)d_in[1];
    const float* b = (const float*)d_in[2];
    float* out = (float*)d_out;

    const int idx_off = out_size / 2;

    cudaFuncSetAttribute(gating_kernel,
                         cudaFuncAttributeMaxDynamicSharedMemorySize,
                         (int)SMEM_BYTES);

    gating_kernel<<<GRID, THREADS, SMEM_BYTES>>>(x, W, b, out, idx_off);
}